// round 9
// baseline (speedup 1.0000x reference)
#include <cuda_runtime.h>
#include <math.h>

#define Bc 2
#define Sc 2048
#define Dc 1024
#define Hc 16
#define DKc 64
#define BSc (Bc*Sc)   // 4096

// Scratch (no allocations allowed)
__device__ float g_qkv[(size_t)BSc * 3 * Dc];      // [B,S,3,H,DK]
__device__ float g_q[(size_t)Bc*Hc*Sc*DKc];        // [B,H,S,DK]
__device__ float g_k[(size_t)Bc*Hc*Sc*DKc];
__device__ float g_v[(size_t)Bc*Hc*Sc*DKc];
__device__ float g_attn[(size_t)BSc * Dc];         // [B,S,D]
__device__ float g_ctab[Sc * 32];                  // RoPE cos table
__device__ float g_stab[Sc * 32];                  // RoPE sin table

__device__ __forceinline__ unsigned f2tf(float x) {
    unsigned r;
    asm("cvt.rna.tf32.f32 %0, %1;" : "=r"(r) : "f"(x));
    return r;
}

__device__ __forceinline__ void mma8(float4& d, uint2 a01, uint2 a23, uint2 b) {
    asm volatile(
        "mma.sync.aligned.m16n8k8.row.col.f32.tf32.tf32.f32 "
        "{%0,%1,%2,%3}, {%4,%5,%6,%7}, {%8,%9}, {%0,%1,%2,%3};\n"
        : "+f"(d.x), "+f"(d.y), "+f"(d.z), "+f"(d.w)
        : "r"(a01.x), "r"(a01.y), "r"(a23.x), "r"(a23.y), "r"(b.x), "r"(b.y));
}

// ---------------------------------------------------------------------------
// tf32 tensor-core GEMM with register-prefetch pipelining.
// C[M,N] = A[M,K] @ B[K,N], tiles 128x128x32, 8 warps (2x4).
// Loop: pack(regs->smem) / bar / LDG next tile (in flight) / mma / bar.
// ---------------------------------------------------------------------------
#define AS 36   // A-pack rowgroup stride in uint2 (36 mod 32 = 4 -> bank-safe)

__global__ __launch_bounds__(256)
void tgemm_kernel(const float* __restrict__ A,
                  const float* __restrict__ B,
                  float* __restrict__ C,
                  int M, int N, int K) {
    __shared__ uint2 Ap[64 * AS];    // pairs {A[r][k], A[r+8][k]} : [rowgrp][k]
    __shared__ uint2 Bp[64 * 32];    // pairs {B[k][n], B[k+4][n]} : [mma][lane]

    const int tid = threadIdx.x;
    const int lane = tid & 31;
    const int w = tid >> 5;          // warp 0..7
    const int g = lane >> 2;
    const int tig = lane & 3;
    const int wm = w >> 2;           // 0..1  (m offset wm*64)
    const int wn = w & 3;            // 0..3  (n offset wn*32)
    const int m0 = blockIdx.y << 7;
    const int n0 = blockIdx.x << 7;

    // Per-thread load geometry (fixed across iterations)
    const int rgA0 = tid >> 3;                   // it=0 rowgroup
    const int kqA = tid & 7;                     // A k-quad
    const int rA0 = m0 + (rgA0 >> 3) * 16 + (rgA0 & 7);
    const int rgA1 = (tid + 256) >> 3;           // it=1 rowgroup
    const int rA1 = m0 + (rgA1 >> 3) * 16 + (rgA1 & 7);

    const int cqB = tid & 31;                    // B n-quad
    const int tgB = (tid >> 5) & 3;
    const int ksB0 = tid >> 7;                   // it=0 k-octet (0..1)
    const int ksB1 = ksB0 + 2;                   // it=1 k-octet (2..3)

    float4 pa[4], pb[4];
    // ---- prologue: prefetch k0 = 0 ----
    {
        pa[0] = *(const float4*)&A[(size_t)rA0 * K + kqA * 4];
        pa[1] = *(const float4*)&A[(size_t)(rA0 + 8) * K + kqA * 4];
        pa[2] = *(const float4*)&A[(size_t)rA1 * K + kqA * 4];
        pa[3] = *(const float4*)&A[(size_t)(rA1 + 8) * K + kqA * 4];
        int row0 = ksB0 * 8 + tgB;
        int row1 = ksB1 * 8 + tgB;
        pb[0] = *(const float4*)&B[(size_t)row0 * N + n0 + cqB * 4];
        pb[1] = *(const float4*)&B[(size_t)(row0 + 4) * N + n0 + cqB * 4];
        pb[2] = *(const float4*)&B[(size_t)row1 * N + n0 + cqB * 4];
        pb[3] = *(const float4*)&B[(size_t)(row1 + 4) * N + n0 + cqB * 4];
    }

    float4 acc[4][4];
#pragma unroll
    for (int i = 0; i < 4; i++)
#pragma unroll
        for (int j = 0; j < 4; j++) acc[i][j] = make_float4(0.f, 0.f, 0.f, 0.f);

    for (int k0 = 0; k0 < K; k0 += 32) {
        // ---- pack prefetched regs into smem ----
#pragma unroll
        for (int it = 0; it < 2; it++) {
            int rg = it ? rgA1 : rgA0;
            float4 f0 = pa[it * 2], f1 = pa[it * 2 + 1];
            uint4 u0 = make_uint4(f2tf(f0.x), f2tf(f1.x), f2tf(f0.y), f2tf(f1.y));
            uint4 u1 = make_uint4(f2tf(f0.z), f2tf(f1.z), f2tf(f0.w), f2tf(f1.w));
            *(uint4*)&Ap[rg * AS + kqA * 4 + 0] = u0;
            *(uint4*)&Ap[rg * AS + kqA * 4 + 2] = u1;
        }
#pragma unroll
        for (int it = 0; it < 2; it++) {
            int ks = it ? ksB1 : ksB0;
            float4 f0 = pb[it * 2], f1 = pb[it * 2 + 1];
            float fa[4] = {f0.x, f0.y, f0.z, f0.w};
            float fb[4] = {f1.x, f1.y, f1.z, f1.w};
#pragma unroll
            for (int i = 0; i < 4; i++) {
                int col = cqB * 4 + i;
                Bp[(ks * 16 + (col >> 3)) * 32 + (col & 7) * 4 + tgB] =
                    make_uint2(f2tf(fa[i]), f2tf(fb[i]));
            }
        }
        __syncthreads();

        // ---- prefetch next k-tile (LDGs in flight during mma) ----
        const int kn = k0 + 32;
        if (kn < K) {
            pa[0] = *(const float4*)&A[(size_t)rA0 * K + kn + kqA * 4];
            pa[1] = *(const float4*)&A[(size_t)(rA0 + 8) * K + kn + kqA * 4];
            pa[2] = *(const float4*)&A[(size_t)rA1 * K + kn + kqA * 4];
            pa[3] = *(const float4*)&A[(size_t)(rA1 + 8) * K + kn + kqA * 4];
            int row0 = kn + ksB0 * 8 + tgB;
            int row1 = kn + ksB1 * 8 + tgB;
            pb[0] = *(const float4*)&B[(size_t)row0 * N + n0 + cqB * 4];
            pb[1] = *(const float4*)&B[(size_t)(row0 + 4) * N + n0 + cqB * 4];
            pb[2] = *(const float4*)&B[(size_t)row1 * N + n0 + cqB * 4];
            pb[3] = *(const float4*)&B[(size_t)(row1 + 4) * N + n0 + cqB * 4];
        }

        // ---- 16 mma per k-octet per warp ----
#pragma unroll
        for (int ks = 0; ks < 4; ks++) {
            uint2 bfr[4];
#pragma unroll
            for (int nt = 0; nt < 4; nt++)
                bfr[nt] = Bp[(ks * 16 + wn * 4 + nt) * 32 + lane];
#pragma unroll
            for (int mt = 0; mt < 4; mt++) {
                uint2 a01 = Ap[(wm * 32 + mt * 8 + g) * AS + ks * 8 + tig];
                uint2 a23 = Ap[(wm * 32 + mt * 8 + g) * AS + ks * 8 + tig + 4];
#pragma unroll
                for (int nt = 0; nt < 4; nt++)
                    mma8(acc[mt][nt], a01, a23, bfr[nt]);
            }
        }
        __syncthreads();   // mma reads done before next pack overwrites
    }

    // ---- epilogue ----
#pragma unroll
    for (int mt = 0; mt < 4; mt++) {
        int row = m0 + wm * 64 + mt * 16 + g;
#pragma unroll
        for (int nt = 0; nt < 4; nt++) {
            int col = n0 + wn * 32 + nt * 8 + 2 * tig;
            *(float2*)&C[(size_t)row * N + col] =
                make_float2(acc[mt][nt].x, acc[mt][nt].y);
            *(float2*)&C[(size_t)(row + 8) * N + col] =
                make_float2(acc[mt][nt].z, acc[mt][nt].w);
        }
    }
}

// ---------------------------------------------------------------------------
// RoPE table precompute (exact same math as reference path)
// ---------------------------------------------------------------------------
__global__ void rope_table_kernel() {
    int idx = blockIdx.x * blockDim.x + threadIdx.x;   // s*32 + d2
    int d2 = idx & 31;
    int s = idx >> 5;
    float invf = 1.0f / powf(10000.0f, (float)d2 * (1.0f / 32.0f));
    float ang = (float)s * invf;
    float sn, c;
    sincosf(ang, &sn, &c);
    g_ctab[idx] = c;
    g_stab[idx] = sn;
}

// ---------------------------------------------------------------------------
// RoPE + split heads, table-driven
// ---------------------------------------------------------------------------
__global__ void rope_split_kernel(const float* __restrict__ qkv,
                                  float* __restrict__ Q,
                                  float* __restrict__ Kp,
                                  float* __restrict__ V) {
    int idx = blockIdx.x * blockDim.x + threadIdx.x;  // [b][s][h][d]
    int d = idx & 63;
    int h = (idx >> 6) & (Hc - 1);
    int s = (idx >> 10) & (Sc - 1);
    int b = idx >> 21;

    const float* base = qkv + (size_t)(b * Sc + s) * 3 * Dc + h * DKc;
    float qv = base[d];
    float kv = base[Dc + d];
    float vv = base[2 * Dc + d];

    int d2 = d & 31;
    float c = g_ctab[s * 32 + d2];
    float sn = g_stab[s * 32 + d2];

    int dp = d ^ 32;            // rotate_half partner
    float qp = base[dp];
    float kp = base[Dc + dp];
    float sgn = (d < 32) ? -1.0f : 1.0f;

    float qo = qv * c + sgn * qp * sn;
    float ko = kv * c + sgn * kp * sn;

    size_t o = ((size_t)(b * Hc + h) * Sc + s) * DKc + d;
    Q[o] = qo;
    Kp[o] = ko;
    V[o] = vv;
}

// ---------------------------------------------------------------------------
// Flash attention (unchanged from R7/R8 — measured 255us)
// ---------------------------------------------------------------------------
#define UQ 68               // a-fragment row-group stride in uint2 (bank-safe)
#define QTILES (Sc / 128)   // 16

__global__ __launch_bounds__(256, 2)
void flash_attn_kernel(const float* __restrict__ Q,
                       const float* __restrict__ K,
                       const float* __restrict__ V,
                       float* __restrict__ Out) {
    extern __shared__ uint2 sm2[];
    uint2* Qp = sm2;                  // [64 rowgrps][UQ]
    uint2* Pp = Qp + 64 * UQ;         // [64 rowgrps][UQ]
    uint2* Kp = Pp + 64 * UQ;         // [64 mma][32 lane]
    uint2* Vp = Kp + 2048;            // [64 mma][32 lane]

    const int tid = threadIdx.x;      // 256 threads
    const int lane = tid & 31;
    const int w = tid >> 5;           // warp 0..7
    const int g = lane >> 2;
    const int tig = lane & 3;

    // Heavy-first scheduling: qt descending with blockIdx.x
    const int id = blockIdx.x;
    const int bh = id & 31;                  // b*H + h
    const int qt = (QTILES - 1) - (id >> 5);
    const int q0 = qt * 128;

    const float* Qb = Q + (size_t)bh * Sc * DKc;
    const float* Kb = K + (size_t)bh * Sc * DKc;
    const float* Vb = V + (size_t)bh * Sc * DKc;

    // ---- Q pack prologue: pairs {Q[r][d], Q[r+8][d]}, pre-scaled ----
#pragma unroll
    for (int it = 0; it < 4; it++) {
        int e = tid + it * 256;        // 1024 assignments
        int rg = e >> 4;               // rowgroup 0..63
        int dq = e & 15;               // d-quad
        int r0 = q0 + (rg >> 3) * 16 + (rg & 7);
        float4 f0 = *(const float4*)&Qb[(size_t)r0 * DKc + dq * 4];
        float4 f1 = *(const float4*)&Qb[(size_t)(r0 + 8) * DKc + dq * 4];
        uint4 u0 = make_uint4(f2tf(f0.x * 0.125f), f2tf(f1.x * 0.125f),
                              f2tf(f0.y * 0.125f), f2tf(f1.y * 0.125f));
        uint4 u1 = make_uint4(f2tf(f0.z * 0.125f), f2tf(f1.z * 0.125f),
                              f2tf(f0.w * 0.125f), f2tf(f1.w * 0.125f));
        *(uint4*)&Qp[rg * UQ + dq * 4 + 0] = u0;
        *(uint4*)&Qp[rg * UQ + dq * 4 + 2] = u1;
    }

    float4 s[8], o[8];
#pragma unroll
    for (int t = 0; t < 8; t++) o[t] = make_float4(0.f, 0.f, 0.f, 0.f);
    float mrow0 = -INFINITY, mrow1 = -INFINITY, lrow0 = 0.f, lrow1 = 0.f;

    const int nkt = 2 * qt + 2;       // causal: key tiles of 64
    for (int kt = 0; kt < nkt; kt++) {
        const int k0 = kt * 64;

        __syncthreads();   // prior iter's reads of Kp/Vp/Pp done

        // ---- K pack: b-frag pairs ----
#pragma unroll
        for (int it = 0; it < 2; it++) {
            int e = tid + it * 256;    // 512 assignments
            int key = e & 63;
            int ks = e >> 6;           // 0..7
            const float* src = &Kb[(size_t)(k0 + key) * DKc + ks * 8];
            float4 f0 = *(const float4*)src;
            float4 f1 = *(const float4*)(src + 4);
            int m = ks * 8 + (key >> 3);
            int lb = (key & 7) * 4;
            uint4 u0 = make_uint4(f2tf(f0.x), f2tf(f1.x), f2tf(f0.y), f2tf(f1.y));
            uint4 u1 = make_uint4(f2tf(f0.z), f2tf(f1.z), f2tf(f0.w), f2tf(f1.w));
            *(uint4*)&Kp[m * 32 + lb + 0] = u0;
            *(uint4*)&Kp[m * 32 + lb + 2] = u1;
        }
        // ---- V pack: b-frag pairs ----
#pragma unroll
        for (int it = 0; it < 2; it++) {
            int e = tid + it * 256;    // 512 assignments
            int cq = e & 15;
            int tg = (e >> 4) & 3;
            int js = e >> 6;           // 0..7
            int r0 = k0 + js * 8 + tg;
            float4 f0 = *(const float4*)&Vb[(size_t)r0 * DKc + cq * 4];
            float4 f1 = *(const float4*)&Vb[(size_t)(r0 + 4) * DKc + cq * 4];
            float fa[4] = {f0.x, f0.y, f0.z, f0.w};
            float fb[4] = {f1.x, f1.y, f1.z, f1.w};
#pragma unroll
            for (int i = 0; i < 4; i++) {
                int col = cq * 4 + i;
                Vp[(js * 8 + (col >> 3)) * 32 + (col & 7) * 4 + tg] =
                    make_uint2(f2tf(fa[i]), f2tf(fb[i]));
            }
        }
        __syncthreads();

        // ---- S = (Q*scale) @ K^T ----
#pragma unroll
        for (int t = 0; t < 8; t++) s[t] = make_float4(0.f, 0.f, 0.f, 0.f);
#pragma unroll
        for (int ks = 0; ks < 8; ks++) {
            uint2 a01 = Qp[(w * 8 + g) * UQ + ks * 8 + tig];
            uint2 a23 = Qp[(w * 8 + g) * UQ + ks * 8 + tig + 4];
#pragma unroll
            for (int t = 0; t < 8; t++)
                mma8(s[t], a01, a23, Kp[(ks * 8 + t) * 32 + lane]);
        }

        // Causal mask — only on the last two key tiles
        if (kt >= 2 * qt) {
            const int r0 = q0 + w * 16 + g;
            const int r1 = r0 + 8;
#pragma unroll
            for (int t = 0; t < 8; t++) {
                int c0 = k0 + t * 8 + 2 * tig;
                if (c0 > r0)     s[t].x = -INFINITY;
                if (c0 + 1 > r0) s[t].y = -INFINITY;
                if (c0 > r1)     s[t].z = -INFINITY;
                if (c0 + 1 > r1) s[t].w = -INFINITY;
            }
        }

        // ---- Online softmax on fragments ----
        float mx0 = -INFINITY, mx1 = -INFINITY;
#pragma unroll
        for (int t = 0; t < 8; t++) {
            mx0 = fmaxf(mx0, fmaxf(s[t].x, s[t].y));
            mx1 = fmaxf(mx1, fmaxf(s[t].z, s[t].w));
        }
        mx0 = fmaxf(mx0, __shfl_xor_sync(0xffffffffu, mx0, 1));
        mx0 = fmaxf(mx0, __shfl_xor_sync(0xffffffffu, mx0, 2));
        mx1 = fmaxf(mx1, __shfl_xor_sync(0xffffffffu, mx1, 1));
        mx1 = fmaxf(mx1, __shfl_xor_sync(0xffffffffu, mx1, 2));
        float mnew0 = fmaxf(mrow0, mx0);
        float mnew1 = fmaxf(mrow1, mx1);
        float cr0 = __expf(mrow0 - mnew0);
        float cr1 = __expf(mrow1 - mnew1);
        float sum0 = 0.f, sum1 = 0.f;
#pragma unroll
        for (int t = 0; t < 8; t++) {
            s[t].x = __expf(s[t].x - mnew0);
            s[t].y = __expf(s[t].y - mnew0);
            s[t].z = __expf(s[t].z - mnew1);
            s[t].w = __expf(s[t].w - mnew1);
            sum0 += s[t].x + s[t].y;
            sum1 += s[t].z + s[t].w;
        }
        sum0 += __shfl_xor_sync(0xffffffffu, sum0, 1);
        sum0 += __shfl_xor_sync(0xffffffffu, sum0, 2);
        sum1 += __shfl_xor_sync(0xffffffffu, sum1, 1);
        sum1 += __shfl_xor_sync(0xffffffffu, sum1, 2);
        lrow0 = lrow0 * cr0 + sum0;
        lrow1 = lrow1 * cr1 + sum1;
        mrow0 = mnew0;
        mrow1 = mnew1;
#pragma unroll
        for (int t = 0; t < 8; t++) {
            o[t].x *= cr0; o[t].y *= cr0;
            o[t].z *= cr1; o[t].w *= cr1;
        }

        // ---- Publish P directly in a-fragment pair order ----
#pragma unroll
        for (int t = 0; t < 8; t++) {
            uint4 u = make_uint4(f2tf(s[t].x), f2tf(s[t].z),
                                 f2tf(s[t].y), f2tf(s[t].w));
            *(uint4*)&Pp[(w * 8 + g) * UQ + t * 8 + 2 * tig] = u;
        }
        __syncthreads();

        // ---- O += P @ V ----
#pragma unroll
        for (int js = 0; js < 8; js++) {
            uint2 a01 = Pp[(w * 8 + g) * UQ + js * 8 + tig];
            uint2 a23 = Pp[(w * 8 + g) * UQ + js * 8 + tig + 4];
#pragma unroll
            for (int t = 0; t < 8; t++)
                mma8(o[t], a01, a23, Vp[(js * 8 + t) * 32 + lane]);
        }
    }

    // Normalize and write out as [B,S,H*DK]
    const int b = bh >> 4;
    const int h = bh & 15;
    const float inv0 = 1.0f / lrow0;
    const float inv1 = 1.0f / lrow1;
    const size_t row0 = (size_t)(b * Sc + q0 + w * 16 + g) * Dc + h * DKc;
    const size_t row1 = row0 + 8 * Dc;
#pragma unroll
    for (int t = 0; t < 8; t++) {
        *(float2*)&Out[row0 + t * 8 + 2 * tig] =
            make_float2(o[t].x * inv0, o[t].y * inv0);
        *(float2*)&Out[row1 + t * 8 + 2 * tig] =
            make_float2(o[t].z * inv1, o[t].w * inv1);
    }
}

// ---------------------------------------------------------------------------
extern "C" void kernel_launch(void* const* d_in, const int* in_sizes, int n_in,
                              void* d_out, int out_size) {
    const float* x    = (const float*)d_in[0];   // [B,S,D]
    const float* Wqkv = (const float*)d_in[1];   // [D, 3D]
    const float* Wo   = (const float*)d_in[2];   // [D, D]
    float* out = (float*)d_out;

    float *qkv, *q, *k, *v, *attn;
    cudaGetSymbolAddress((void**)&qkv,  g_qkv);
    cudaGetSymbolAddress((void**)&q,    g_q);
    cudaGetSymbolAddress((void**)&k,    g_k);
    cudaGetSymbolAddress((void**)&v,    g_v);
    cudaGetSymbolAddress((void**)&attn, g_attn);

    // 0. RoPE tables
    rope_table_kernel<<<(Sc * 32) / 256, 256>>>();

    // 1. QKV projection: [4096,1024] @ [1024,3072]  (tf32, pipelined)
    tgemm_kernel<<<dim3(3 * Dc / 128, BSc / 128), 256>>>(x, Wqkv, qkv, BSc, 3 * Dc, Dc);

    // 2. RoPE + head split (table-driven)
    rope_split_kernel<<<(Bc * Sc * Hc * DKc) / 256, 256>>>(qkv, q, k, v);

    // 3. Causal flash attention (tf32, fragment-packed smem)
    const int smem = (64 * UQ * 2 + 2048 * 2) * (int)sizeof(uint2);  // 102400 B
    cudaFuncSetAttribute(flash_attn_kernel,
                         cudaFuncAttributeMaxDynamicSharedMemorySize, smem);
    flash_attn_kernel<<<32 * QTILES, 256, smem>>>(q, k, v, attn);

    // 4. Output projection: [4096,1024] @ [1024,1024]  (tf32, pipelined)
    tgemm_kernel<<<dim3(Dc / 128, BSc / 128), 256>>>(attn, Wo, out, BSc, Dc, Dc);
}

// round 10
// speedup vs baseline: 1.6108x; 1.6108x over previous
#include <cuda_runtime.h>
#include <math.h>

#define Bc 2
#define Sc 2048
#define Dc 1024
#define Hc 16
#define DKc 64
#define BSc (Bc*Sc)   // 4096

// Scratch (no allocations allowed)
__device__ float g_qkv[(size_t)BSc * 3 * Dc];      // [B,S,3,H,DK]
__device__ float g_q[(size_t)Bc*Hc*Sc*DKc];        // [B,H,S,DK]
__device__ float g_k[(size_t)Bc*Hc*Sc*DKc];
__device__ float g_v[(size_t)Bc*Hc*Sc*DKc];
__device__ float g_attn[(size_t)BSc * Dc];         // [B,S,D]
__device__ float g_ctab[Sc * 32];                  // RoPE cos table
__device__ float g_stab[Sc * 32];                  // RoPE sin table

// Packed tf32 tile buffers (tile-major, fragment order)
__device__ uint2 g_apk_x[(size_t)BSc * Dc / 2];        // 2M uint2
__device__ uint2 g_bpk_qkv[(size_t)Dc * 3 * Dc / 2];   // 1.5M
__device__ uint2 g_apk_attn[(size_t)BSc * Dc / 2];     // 2M
__device__ uint2 g_bpk_wo[(size_t)Dc * Dc / 2];        // 0.5M

__device__ __forceinline__ unsigned f2tf(float x) {
    unsigned r;
    asm("cvt.rna.tf32.f32 %0, %1;" : "=r"(r) : "f"(x));
    return r;
}

__device__ __forceinline__ void mma8(float4& d, uint2 a01, uint2 a23, uint2 b) {
    asm volatile(
        "mma.sync.aligned.m16n8k8.row.col.f32.tf32.tf32.f32 "
        "{%0,%1,%2,%3}, {%4,%5,%6,%7}, {%8,%9}, {%0,%1,%2,%3};\n"
        : "+f"(d.x), "+f"(d.y), "+f"(d.z), "+f"(d.w)
        : "r"(a01.x), "r"(a01.y), "r"(a23.x), "r"(a23.y), "r"(b.x), "r"(b.y));
}

__device__ __forceinline__ void cpa16(unsigned dst, const void* src) {
    asm volatile("cp.async.cg.shared.global [%0], [%1], 16;"
                 :: "r"(dst), "l"(src));
}

// ---------------------------------------------------------------------------
// Pre-pack A[M,K=1024] -> tile-major a-fragment pairs.
// Tile (mt,kt): 2048 uint2 at (mt*32+kt)*2048; pos = rg*32 + k;
// value = { f2tf(A[r][kt*32+k]), f2tf(A[r+8][kt*32+k]) },
// r = mt*128 + (rg>>3)*16 + (rg&7).
// ---------------------------------------------------------------------------
__global__ void prepackA_kernel(const float* __restrict__ A,
                                uint2* __restrict__ out, int K) {
    int idx = blockIdx.x * blockDim.x + threadIdx.x;
    int k = idx & 31;
    int rg = (idx >> 5) & 63;
    int ck = idx >> 11;
    int kt = ck & 31;              // K=1024 -> KT=32
    int mt = ck >> 5;
    int r = mt * 128 + ((rg >> 3) << 4) + (rg & 7);
    int col = kt * 32 + k;
    out[idx] = make_uint2(f2tf(A[(size_t)r * K + col]),
                          f2tf(A[(size_t)(r + 8) * K + col]));
}

// ---------------------------------------------------------------------------
// Pre-pack B[K=1024,N] -> tile-major b-fragment pairs.
// Tile (nt,kt): 2048 uint2 at (nt*32+kt)*2048;
// pos = (ks*16 + (col>>3))*32 + (col&7)*4 + tg;
// value = { f2tf(B[kt*32+ks*8+tg][nt*128+col]), f2tf(B[+4 row][same col]) }.
// ---------------------------------------------------------------------------
__global__ void prepackB_kernel(const float* __restrict__ B,
                                uint2* __restrict__ out, int N) {
    int idx = blockIdx.x * blockDim.x + threadIdx.x;
    int pos = idx & 2047;
    int ck = idx >> 11;
    int kt = ck & 31;
    int nt = ck >> 5;
    int tg = pos & 3;
    int col = (((pos >> 5) & 15) << 3) + ((pos >> 2) & 7);
    int ks = pos >> 9;
    int row = kt * 32 + ks * 8 + tg;
    int c = nt * 128 + col;
    out[idx] = make_uint2(f2tf(B[(size_t)row * N + c]),
                          f2tf(B[(size_t)(row + 4) * N + c]));
}

// ---------------------------------------------------------------------------
// tf32 GEMM on prepacked tiles, cp.async double-buffered. K=1024 fixed.
// smem/buf: A 64*36 uint2 (padded stride 36), B 64*32 uint2.
// ---------------------------------------------------------------------------
#define AS 36
#define BUFA_BYTES (64 * AS * 8)        // 18432
#define BUFB_BYTES (64 * 32 * 8)        // 16384
#define SMEM_TOTAL (2 * (BUFA_BYTES + BUFB_BYTES))   // 69632

__global__ __launch_bounds__(256, 2)
void tgemm_packed(const uint2* __restrict__ Apk,
                  const uint2* __restrict__ Bpk,
                  float* __restrict__ C, int M, int N) {
    extern __shared__ char smraw[];
    unsigned smem_u;
    asm("{ .reg .u64 t; cvta.to.shared.u64 t, %1; cvt.u32.u64 %0, t; }"
        : "=r"(smem_u) : "l"(smraw));
    const unsigned sA0 = smem_u;
    const unsigned sB0 = smem_u + 2 * BUFA_BYTES;

    const int tid = threadIdx.x;
    const int lane = tid & 31;
    const int w = tid >> 5;
    const int g = lane >> 2;
    const int tig = lane & 3;
    const int wm = w >> 2;
    const int wn = w & 3;
    const int mt_blk = blockIdx.y;
    const int nt_blk = blockIdx.x;

    const uint2* Abase = Apk + (size_t)mt_blk * 32 * 2048;   // tiles kt=0..31
    const uint2* Bbase = Bpk + (size_t)nt_blk * 32 * 2048;

    // issue cp.asyncs for k-tile kt into buffer b
    auto issue = [&](int kt, int b) {
        const uint2* at = Abase + (size_t)kt * 2048;
        const uint2* bt = Bbase + (size_t)kt * 2048;
        unsigned dA = sA0 + b * BUFA_BYTES;
        unsigned dB = sB0 + b * BUFB_BYTES;
#pragma unroll
        for (int i = 0; i < 4; i++) {
            int e = tid + i * 256;            // 16B chunk id, 0..1023
            int rg = e >> 4, c = e & 15;
            cpa16(dA + rg * (AS * 8) + c * 16, at + e * 2);
        }
#pragma unroll
        for (int i = 0; i < 4; i++) {
            int e = tid + i * 256;
            cpa16(dB + e * 16, bt + e * 2);
        }
        asm volatile("cp.async.commit_group;");
    };

    issue(0, 0);

    float4 acc[4][4];
#pragma unroll
    for (int i = 0; i < 4; i++)
#pragma unroll
        for (int j = 0; j < 4; j++) acc[i][j] = make_float4(0.f, 0.f, 0.f, 0.f);

    for (int kt = 0; kt < 32; kt++) {
        const int b = kt & 1;
        if (kt + 1 < 32) {
            issue(kt + 1, b ^ 1);
            asm volatile("cp.async.wait_group 1;");
        } else {
            asm volatile("cp.async.wait_group 0;");
        }
        __syncthreads();

        const uint2* Ap = (const uint2*)(smraw + (size_t)b * BUFA_BYTES);
        const uint2* Bp = (const uint2*)(smraw + 2 * BUFA_BYTES
                                               + (size_t)b * BUFB_BYTES);
#pragma unroll
        for (int ks = 0; ks < 4; ks++) {
            uint2 bfr[4];
#pragma unroll
            for (int nt = 0; nt < 4; nt++)
                bfr[nt] = Bp[(ks * 16 + wn * 4 + nt) * 32 + lane];
#pragma unroll
            for (int mt = 0; mt < 4; mt++) {
                uint2 a01 = Ap[(wm * 32 + mt * 8 + g) * AS + ks * 8 + tig];
                uint2 a23 = Ap[(wm * 32 + mt * 8 + g) * AS + ks * 8 + tig + 4];
#pragma unroll
                for (int nt = 0; nt < 4; nt++)
                    mma8(acc[mt][nt], a01, a23, bfr[nt]);
            }
        }
        __syncthreads();   // mma reads done before this buffer is refilled
    }

    // ---- epilogue ----
    const int m0 = mt_blk << 7;
    const int n0 = nt_blk << 7;
#pragma unroll
    for (int mt = 0; mt < 4; mt++) {
        int row = m0 + wm * 64 + mt * 16 + g;
#pragma unroll
        for (int nt = 0; nt < 4; nt++) {
            int col = n0 + wn * 32 + nt * 8 + 2 * tig;
            *(float2*)&C[(size_t)row * N + col] =
                make_float2(acc[mt][nt].x, acc[mt][nt].y);
            *(float2*)&C[(size_t)(row + 8) * N + col] =
                make_float2(acc[mt][nt].z, acc[mt][nt].w);
        }
    }
}

// ---------------------------------------------------------------------------
// RoPE table precompute (exact same math as reference path)
// ---------------------------------------------------------------------------
__global__ void rope_table_kernel() {
    int idx = blockIdx.x * blockDim.x + threadIdx.x;   // s*32 + d2
    int d2 = idx & 31;
    int s = idx >> 5;
    float invf = 1.0f / powf(10000.0f, (float)d2 * (1.0f / 32.0f));
    float ang = (float)s * invf;
    float sn, c;
    sincosf(ang, &sn, &c);
    g_ctab[idx] = c;
    g_stab[idx] = sn;
}

// ---------------------------------------------------------------------------
// RoPE + split heads, table-driven
// ---------------------------------------------------------------------------
__global__ void rope_split_kernel(const float* __restrict__ qkv,
                                  float* __restrict__ Q,
                                  float* __restrict__ Kp,
                                  float* __restrict__ V) {
    int idx = blockIdx.x * blockDim.x + threadIdx.x;  // [b][s][h][d]
    int d = idx & 63;
    int h = (idx >> 6) & (Hc - 1);
    int s = (idx >> 10) & (Sc - 1);
    int b = idx >> 21;

    const float* base = qkv + (size_t)(b * Sc + s) * 3 * Dc + h * DKc;
    float qv = base[d];
    float kv = base[Dc + d];
    float vv = base[2 * Dc + d];

    int d2 = d & 31;
    float c = g_ctab[s * 32 + d2];
    float sn = g_stab[s * 32 + d2];

    int dp = d ^ 32;            // rotate_half partner
    float qp = base[dp];
    float kp = base[Dc + dp];
    float sgn = (d < 32) ? -1.0f : 1.0f;

    float qo = qv * c + sgn * qp * sn;
    float ko = kv * c + sgn * kp * sn;

    size_t o = ((size_t)(b * Hc + h) * Sc + s) * DKc + d;
    Q[o] = qo;
    Kp[o] = ko;
    V[o] = vv;
}

// ---------------------------------------------------------------------------
// Flash attention (unchanged — measured 255us, stable)
// ---------------------------------------------------------------------------
#define UQ 68               // a-fragment row-group stride in uint2 (bank-safe)
#define QTILES (Sc / 128)   // 16

__global__ __launch_bounds__(256, 2)
void flash_attn_kernel(const float* __restrict__ Q,
                       const float* __restrict__ K,
                       const float* __restrict__ V,
                       float* __restrict__ Out) {
    extern __shared__ uint2 sm2[];
    uint2* Qp = sm2;                  // [64 rowgrps][UQ]
    uint2* Pp = Qp + 64 * UQ;         // [64 rowgrps][UQ]
    uint2* Kp = Pp + 64 * UQ;         // [64 mma][32 lane]
    uint2* Vp = Kp + 2048;            // [64 mma][32 lane]

    const int tid = threadIdx.x;      // 256 threads
    const int lane = tid & 31;
    const int w = tid >> 5;           // warp 0..7
    const int g = lane >> 2;
    const int tig = lane & 3;

    // Heavy-first scheduling: qt descending with blockIdx.x
    const int id = blockIdx.x;
    const int bh = id & 31;                  // b*H + h
    const int qt = (QTILES - 1) - (id >> 5);
    const int q0 = qt * 128;

    const float* Qb = Q + (size_t)bh * Sc * DKc;
    const float* Kb = K + (size_t)bh * Sc * DKc;
    const float* Vb = V + (size_t)bh * Sc * DKc;

    // ---- Q pack prologue: pairs {Q[r][d], Q[r+8][d]}, pre-scaled ----
#pragma unroll
    for (int it = 0; it < 4; it++) {
        int e = tid + it * 256;        // 1024 assignments
        int rg = e >> 4;               // rowgroup 0..63
        int dq = e & 15;               // d-quad
        int r0 = q0 + (rg >> 3) * 16 + (rg & 7);
        float4 f0 = *(const float4*)&Qb[(size_t)r0 * DKc + dq * 4];
        float4 f1 = *(const float4*)&Qb[(size_t)(r0 + 8) * DKc + dq * 4];
        uint4 u0 = make_uint4(f2tf(f0.x * 0.125f), f2tf(f1.x * 0.125f),
                              f2tf(f0.y * 0.125f), f2tf(f1.y * 0.125f));
        uint4 u1 = make_uint4(f2tf(f0.z * 0.125f), f2tf(f1.z * 0.125f),
                              f2tf(f0.w * 0.125f), f2tf(f1.w * 0.125f));
        *(uint4*)&Qp[rg * UQ + dq * 4 + 0] = u0;
        *(uint4*)&Qp[rg * UQ + dq * 4 + 2] = u1;
    }

    float4 s[8], o[8];
#pragma unroll
    for (int t = 0; t < 8; t++) o[t] = make_float4(0.f, 0.f, 0.f, 0.f);
    float mrow0 = -INFINITY, mrow1 = -INFINITY, lrow0 = 0.f, lrow1 = 0.f;

    const int nkt = 2 * qt + 2;       // causal: key tiles of 64
    for (int kt = 0; kt < nkt; kt++) {
        const int k0 = kt * 64;

        __syncthreads();   // prior iter's reads of Kp/Vp/Pp done

        // ---- K pack: b-frag pairs ----
#pragma unroll
        for (int it = 0; it < 2; it++) {
            int e = tid + it * 256;    // 512 assignments
            int key = e & 63;
            int ks = e >> 6;           // 0..7
            const float* src = &Kb[(size_t)(k0 + key) * DKc + ks * 8];
            float4 f0 = *(const float4*)src;
            float4 f1 = *(const float4*)(src + 4);
            int m = ks * 8 + (key >> 3);
            int lb = (key & 7) * 4;
            uint4 u0 = make_uint4(f2tf(f0.x), f2tf(f1.x), f2tf(f0.y), f2tf(f1.y));
            uint4 u1 = make_uint4(f2tf(f0.z), f2tf(f1.z), f2tf(f0.w), f2tf(f1.w));
            *(uint4*)&Kp[m * 32 + lb + 0] = u0;
            *(uint4*)&Kp[m * 32 + lb + 2] = u1;
        }
        // ---- V pack: b-frag pairs ----
#pragma unroll
        for (int it = 0; it < 2; it++) {
            int e = tid + it * 256;    // 512 assignments
            int cq = e & 15;
            int tg = (e >> 4) & 3;
            int js = e >> 6;           // 0..7
            int r0 = k0 + js * 8 + tg;
            float4 f0 = *(const float4*)&Vb[(size_t)r0 * DKc + cq * 4];
            float4 f1 = *(const float4*)&Vb[(size_t)(r0 + 4) * DKc + cq * 4];
            float fa[4] = {f0.x, f0.y, f0.z, f0.w};
            float fb[4] = {f1.x, f1.y, f1.z, f1.w};
#pragma unroll
            for (int i = 0; i < 4; i++) {
                int col = cq * 4 + i;
                Vp[(js * 8 + (col >> 3)) * 32 + (col & 7) * 4 + tg] =
                    make_uint2(f2tf(fa[i]), f2tf(fb[i]));
            }
        }
        __syncthreads();

        // ---- S = (Q*scale) @ K^T ----
#pragma unroll
        for (int t = 0; t < 8; t++) s[t] = make_float4(0.f, 0.f, 0.f, 0.f);
#pragma unroll
        for (int ks = 0; ks < 8; ks++) {
            uint2 a01 = Qp[(w * 8 + g) * UQ + ks * 8 + tig];
            uint2 a23 = Qp[(w * 8 + g) * UQ + ks * 8 + tig + 4];
#pragma unroll
            for (int t = 0; t < 8; t++)
                mma8(s[t], a01, a23, Kp[(ks * 8 + t) * 32 + lane]);
        }

        // Causal mask — only on the last two key tiles
        if (kt >= 2 * qt) {
            const int r0 = q0 + w * 16 + g;
            const int r1 = r0 + 8;
#pragma unroll
            for (int t = 0; t < 8; t++) {
                int c0 = k0 + t * 8 + 2 * tig;
                if (c0 > r0)     s[t].x = -INFINITY;
                if (c0 + 1 > r0) s[t].y = -INFINITY;
                if (c0 > r1)     s[t].z = -INFINITY;
                if (c0 + 1 > r1) s[t].w = -INFINITY;
            }
        }

        // ---- Online softmax on fragments ----
        float mx0 = -INFINITY, mx1 = -INFINITY;
#pragma unroll
        for (int t = 0; t < 8; t++) {
            mx0 = fmaxf(mx0, fmaxf(s[t].x, s[t].y));
            mx1 = fmaxf(mx1, fmaxf(s[t].z, s[t].w));
        }
        mx0 = fmaxf(mx0, __shfl_xor_sync(0xffffffffu, mx0, 1));
        mx0 = fmaxf(mx0, __shfl_xor_sync(0xffffffffu, mx0, 2));
        mx1 = fmaxf(mx1, __shfl_xor_sync(0xffffffffu, mx1, 1));
        mx1 = fmaxf(mx1, __shfl_xor_sync(0xffffffffu, mx1, 2));
        float mnew0 = fmaxf(mrow0, mx0);
        float mnew1 = fmaxf(mrow1, mx1);
        float cr0 = __expf(mrow0 - mnew0);
        float cr1 = __expf(mrow1 - mnew1);
        float sum0 = 0.f, sum1 = 0.f;
#pragma unroll
        for (int t = 0; t < 8; t++) {
            s[t].x = __expf(s[t].x - mnew0);
            s[t].y = __expf(s[t].y - mnew0);
            s[t].z = __expf(s[t].z - mnew1);
            s[t].w = __expf(s[t].w - mnew1);
            sum0 += s[t].x + s[t].y;
            sum1 += s[t].z + s[t].w;
        }
        sum0 += __shfl_xor_sync(0xffffffffu, sum0, 1);
        sum0 += __shfl_xor_sync(0xffffffffu, sum0, 2);
        sum1 += __shfl_xor_sync(0xffffffffu, sum1, 1);
        sum1 += __shfl_xor_sync(0xffffffffu, sum1, 2);
        lrow0 = lrow0 * cr0 + sum0;
        lrow1 = lrow1 * cr1 + sum1;
        mrow0 = mnew0;
        mrow1 = mnew1;
#pragma unroll
        for (int t = 0; t < 8; t++) {
            o[t].x *= cr0; o[t].y *= cr0;
            o[t].z *= cr1; o[t].w *= cr1;
        }

        // ---- Publish P directly in a-fragment pair order ----
#pragma unroll
        for (int t = 0; t < 8; t++) {
            uint4 u = make_uint4(f2tf(s[t].x), f2tf(s[t].z),
                                 f2tf(s[t].y), f2tf(s[t].w));
            *(uint4*)&Pp[(w * 8 + g) * UQ + t * 8 + 2 * tig] = u;
        }
        __syncthreads();

        // ---- O += P @ V ----
#pragma unroll
        for (int js = 0; js < 8; js++) {
            uint2 a01 = Pp[(w * 8 + g) * UQ + js * 8 + tig];
            uint2 a23 = Pp[(w * 8 + g) * UQ + js * 8 + tig + 4];
#pragma unroll
            for (int t = 0; t < 8; t++)
                mma8(o[t], a01, a23, Vp[(js * 8 + t) * 32 + lane]);
        }
    }

    // Normalize and write out as [B,S,H*DK]
    const int b = bh >> 4;
    const int h = bh & 15;
    const float inv0 = 1.0f / lrow0;
    const float inv1 = 1.0f / lrow1;
    const size_t row0 = (size_t)(b * Sc + q0 + w * 16 + g) * Dc + h * DKc;
    const size_t row1 = row0 + 8 * Dc;
#pragma unroll
    for (int t = 0; t < 8; t++) {
        *(float2*)&Out[row0 + t * 8 + 2 * tig] =
            make_float2(o[t].x * inv0, o[t].y * inv0);
        *(float2*)&Out[row1 + t * 8 + 2 * tig] =
            make_float2(o[t].z * inv1, o[t].w * inv1);
    }
}

// ---------------------------------------------------------------------------
extern "C" void kernel_launch(void* const* d_in, const int* in_sizes, int n_in,
                              void* d_out, int out_size) {
    const float* x    = (const float*)d_in[0];   // [B,S,D]
    const float* Wqkv = (const float*)d_in[1];   // [D, 3D]
    const float* Wo   = (const float*)d_in[2];   // [D, D]
    float* out = (float*)d_out;

    float *qkv, *q, *k, *v, *attn;
    uint2 *apkx, *bpkq, *apka, *bpkw;
    cudaGetSymbolAddress((void**)&qkv,  g_qkv);
    cudaGetSymbolAddress((void**)&q,    g_q);
    cudaGetSymbolAddress((void**)&k,    g_k);
    cudaGetSymbolAddress((void**)&v,    g_v);
    cudaGetSymbolAddress((void**)&attn, g_attn);
    cudaGetSymbolAddress((void**)&apkx, g_apk_x);
    cudaGetSymbolAddress((void**)&bpkq, g_bpk_qkv);
    cudaGetSymbolAddress((void**)&apka, g_apk_attn);
    cudaGetSymbolAddress((void**)&bpkw, g_bpk_wo);

    // 0. RoPE tables
    rope_table_kernel<<<(Sc * 32) / 256, 256>>>();

    // 1. QKV projection (prepack + cp.async-pipelined tf32 GEMM)
    prepackA_kernel<<<(BSc * Dc / 2) / 256, 256>>>(x, apkx, Dc);
    prepackB_kernel<<<(Dc * 3 * Dc / 2) / 256, 256>>>(Wqkv, bpkq, 3 * Dc);
    cudaFuncSetAttribute(tgemm_packed,
                         cudaFuncAttributeMaxDynamicSharedMemorySize, SMEM_TOTAL);
    tgemm_packed<<<dim3(3 * Dc / 128, BSc / 128), 256, SMEM_TOTAL>>>(
        apkx, bpkq, qkv, BSc, 3 * Dc);

    // 2. RoPE + head split (table-driven)
    rope_split_kernel<<<(Bc * Sc * Hc * DKc) / 256, 256>>>(qkv, q, k, v);

    // 3. Causal flash attention (tf32, fragment-packed smem)
    const int fsmem = (64 * UQ * 2 + 2048 * 2) * (int)sizeof(uint2);  // 102400 B
    cudaFuncSetAttribute(flash_attn_kernel,
                         cudaFuncAttributeMaxDynamicSharedMemorySize, fsmem);
    flash_attn_kernel<<<32 * QTILES, 256, fsmem>>>(q, k, v, attn);

    // 4. Output projection (prepack + cp.async-pipelined tf32 GEMM)
    prepackA_kernel<<<(BSc * Dc / 2) / 256, 256>>>(attn, apka, Dc);
    prepackB_kernel<<<(Dc * Dc / 2) / 256, 256>>>(Wo, bpkw, Dc);
    tgemm_packed<<<dim3(Dc / 128, BSc / 128), 256, SMEM_TOTAL>>>(
        apka, bpkw, out, BSc, Dc);
}

// round 11
// speedup vs baseline: 2.1150x; 1.3130x over previous
#include <cuda_runtime.h>
#include <math.h>

#define Bc 2
#define Sc 2048
#define Dc 1024
#define Hc 16
#define DKc 64
#define BSc (Bc*Sc)   // 4096

// Scratch (no allocations allowed)
__device__ float g_qkv[(size_t)BSc * 3 * Dc];      // [B,S,3,H,DK]
__device__ float g_attn[(size_t)BSc * Dc];         // [B,S,D]
__device__ float g_ctab[Sc * 32];                  // RoPE cos table
__device__ float g_stab[Sc * 32];                  // RoPE sin table

// Packed tf32 tile buffers for the GEMMs (tile-major, fragment order)
__device__ uint2 g_apk_x[(size_t)BSc * Dc / 2];
__device__ uint2 g_bpk_qkv[(size_t)Dc * 3 * Dc / 2];
__device__ uint2 g_apk_attn[(size_t)BSc * Dc / 2];
__device__ uint2 g_bpk_wo[(size_t)Dc * Dc / 2];

// Packed tf32 Q/K/V for flash (written by rope_pack)
__device__ uint2 g_qpk[(size_t)32 * 16 * 4096];    // [bh][qt128] a-frag pairs
__device__ uint2 g_kpk[(size_t)32 * 32 * 2048];    // [bh][kt64]  b-frag pairs
__device__ uint2 g_vpk[(size_t)32 * 32 * 2048];    // [bh][kt64]  b-frag pairs

__device__ __forceinline__ unsigned f2tf(float x) {
    unsigned r;
    asm("cvt.rna.tf32.f32 %0, %1;" : "=r"(r) : "f"(x));
    return r;
}

__device__ __forceinline__ void mma8(float4& d, uint2 a01, uint2 a23, uint2 b) {
    asm volatile(
        "mma.sync.aligned.m16n8k8.row.col.f32.tf32.tf32.f32 "
        "{%0,%1,%2,%3}, {%4,%5,%6,%7}, {%8,%9}, {%0,%1,%2,%3};\n"
        : "+f"(d.x), "+f"(d.y), "+f"(d.z), "+f"(d.w)
        : "r"(a01.x), "r"(a01.y), "r"(a23.x), "r"(a23.y), "r"(b.x), "r"(b.y));
}

__device__ __forceinline__ void cpa16(unsigned dst, const void* src) {
    asm volatile("cp.async.cg.shared.global [%0], [%1], 16;"
                 :: "r"(dst), "l"(src));
}

// ---------------------------------------------------------------------------
// Pre-pack A[M,K=1024] -> tile-major a-fragment pairs (unchanged from R10)
// ---------------------------------------------------------------------------
__global__ void prepackA_kernel(const float* __restrict__ A,
                                uint2* __restrict__ out, int K) {
    int idx = blockIdx.x * blockDim.x + threadIdx.x;
    int k = idx & 31;
    int rg = (idx >> 5) & 63;
    int ck = idx >> 11;
    int kt = ck & 31;
    int mt = ck >> 5;
    int r = mt * 128 + ((rg >> 3) << 4) + (rg & 7);
    int col = kt * 32 + k;
    out[idx] = make_uint2(f2tf(A[(size_t)r * K + col]),
                          f2tf(A[(size_t)(r + 8) * K + col]));
}

// ---------------------------------------------------------------------------
// Pre-pack B[K=1024,N] -> tile-major b-fragment pairs (unchanged from R10)
// ---------------------------------------------------------------------------
__global__ void prepackB_kernel(const float* __restrict__ B,
                                uint2* __restrict__ out, int N) {
    int idx = blockIdx.x * blockDim.x + threadIdx.x;
    int pos = idx & 2047;
    int ck = idx >> 11;
    int kt = ck & 31;
    int nt = ck >> 5;
    int tg = pos & 3;
    int col = (((pos >> 5) & 15) << 3) + ((pos >> 2) & 7);
    int ks = pos >> 9;
    int row = kt * 32 + ks * 8 + tg;
    int c = nt * 128 + col;
    out[idx] = make_uint2(f2tf(B[(size_t)row * N + c]),
                          f2tf(B[(size_t)(row + 4) * N + c]));
}

// ---------------------------------------------------------------------------
// tf32 GEMM on prepacked tiles, cp.async double-buffered (unchanged from R10)
// ---------------------------------------------------------------------------
#define AS 36
#define BUFA_BYTES (64 * AS * 8)
#define BUFB_BYTES (64 * 32 * 8)
#define SMEM_TOTAL (2 * (BUFA_BYTES + BUFB_BYTES))   // 69632

__global__ __launch_bounds__(256, 2)
void tgemm_packed(const uint2* __restrict__ Apk,
                  const uint2* __restrict__ Bpk,
                  float* __restrict__ C, int M, int N) {
    extern __shared__ char smraw[];
    unsigned smem_u;
    asm("{ .reg .u64 t; cvta.to.shared.u64 t, %1; cvt.u32.u64 %0, t; }"
        : "=r"(smem_u) : "l"(smraw));
    const unsigned sA0 = smem_u;
    const unsigned sB0 = smem_u + 2 * BUFA_BYTES;

    const int tid = threadIdx.x;
    const int lane = tid & 31;
    const int w = tid >> 5;
    const int g = lane >> 2;
    const int tig = lane & 3;
    const int wm = w >> 2;
    const int wn = w & 3;
    const int mt_blk = blockIdx.y;
    const int nt_blk = blockIdx.x;

    const uint2* Abase = Apk + (size_t)mt_blk * 32 * 2048;
    const uint2* Bbase = Bpk + (size_t)nt_blk * 32 * 2048;

    auto issue = [&](int kt, int b) {
        const uint2* at = Abase + (size_t)kt * 2048;
        const uint2* bt = Bbase + (size_t)kt * 2048;
        unsigned dA = sA0 + b * BUFA_BYTES;
        unsigned dB = sB0 + b * BUFB_BYTES;
#pragma unroll
        for (int i = 0; i < 4; i++) {
            int e = tid + i * 256;
            int rg = e >> 4, c = e & 15;
            cpa16(dA + rg * (AS * 8) + c * 16, at + e * 2);
        }
#pragma unroll
        for (int i = 0; i < 4; i++) {
            int e = tid + i * 256;
            cpa16(dB + e * 16, bt + e * 2);
        }
        asm volatile("cp.async.commit_group;");
    };

    issue(0, 0);

    float4 acc[4][4];
#pragma unroll
    for (int i = 0; i < 4; i++)
#pragma unroll
        for (int j = 0; j < 4; j++) acc[i][j] = make_float4(0.f, 0.f, 0.f, 0.f);

    for (int kt = 0; kt < 32; kt++) {
        const int b = kt & 1;
        if (kt + 1 < 32) {
            issue(kt + 1, b ^ 1);
            asm volatile("cp.async.wait_group 1;");
        } else {
            asm volatile("cp.async.wait_group 0;");
        }
        __syncthreads();

        const uint2* Ap = (const uint2*)(smraw + (size_t)b * BUFA_BYTES);
        const uint2* Bp = (const uint2*)(smraw + 2 * BUFA_BYTES
                                               + (size_t)b * BUFB_BYTES);
#pragma unroll
        for (int ks = 0; ks < 4; ks++) {
            uint2 bfr[4];
#pragma unroll
            for (int nt = 0; nt < 4; nt++)
                bfr[nt] = Bp[(ks * 16 + wn * 4 + nt) * 32 + lane];
#pragma unroll
            for (int mt = 0; mt < 4; mt++) {
                uint2 a01 = Ap[(wm * 32 + mt * 8 + g) * AS + ks * 8 + tig];
                uint2 a23 = Ap[(wm * 32 + mt * 8 + g) * AS + ks * 8 + tig + 4];
#pragma unroll
                for (int nt = 0; nt < 4; nt++)
                    mma8(acc[mt][nt], a01, a23, bfr[nt]);
            }
        }
        __syncthreads();
    }

    const int m0 = mt_blk << 7;
    const int n0 = nt_blk << 7;
#pragma unroll
    for (int mt = 0; mt < 4; mt++) {
        int row = m0 + wm * 64 + mt * 16 + g;
#pragma unroll
        for (int nt = 0; nt < 4; nt++) {
            int col = n0 + wn * 32 + nt * 8 + 2 * tig;
            *(float2*)&C[(size_t)row * N + col] =
                make_float2(acc[mt][nt].x, acc[mt][nt].y);
            *(float2*)&C[(size_t)(row + 8) * N + col] =
                make_float2(acc[mt][nt].z, acc[mt][nt].w);
        }
    }
}

// ---------------------------------------------------------------------------
// RoPE table precompute (unchanged)
// ---------------------------------------------------------------------------
__global__ void rope_table_kernel() {
    int idx = blockIdx.x * blockDim.x + threadIdx.x;
    int d2 = idx & 31;
    int s = idx >> 5;
    float invf = 1.0f / powf(10000.0f, (float)d2 * (1.0f / 32.0f));
    float ang = (float)s * invf;
    float sn, c;
    sincosf(ang, &sn, &c);
    g_ctab[idx] = c;
    g_stab[idx] = sn;
}

// ---------------------------------------------------------------------------
// RoPE + pack: applies rotary, then writes Q/K/V directly in the tf32
// fragment-packed tile layouts flash consumes. Same arithmetic as before
// (fp32 rope -> [scale] -> cvt.rna.tf32), just relocated.
// ---------------------------------------------------------------------------
__global__ void rope_pack_kernel(const float* __restrict__ qkv,
                                 uint2* __restrict__ Qpk,
                                 uint2* __restrict__ Kpk,
                                 uint2* __restrict__ Vpk) {
    int idx = blockIdx.x * blockDim.x + threadIdx.x;  // [b][s][h][d]
    int d = idx & 63;
    int h = (idx >> 6) & (Hc - 1);
    int s = (idx >> 10) & (Sc - 1);
    int b = idx >> 21;

    const float* base = qkv + (size_t)(b * Sc + s) * 3 * Dc + h * DKc;
    float qv = base[d];
    float kv = base[Dc + d];
    float vv = base[2 * Dc + d];

    int d2 = d & 31;
    float c = g_ctab[s * 32 + d2];
    float sn = g_stab[s * 32 + d2];

    int dp = d ^ 32;
    float qp = base[dp];
    float kp = base[Dc + dp];
    float sgn = (d < 32) ? -1.0f : 1.0f;

    unsigned qo = f2tf((qv * c + sgn * qp * sn) * 0.125f);  // fold 1/sqrt(dk)
    unsigned ko = f2tf(kv * c + sgn * kp * sn);
    unsigned vo = f2tf(vv);

    const int bh = b * Hc + h;

    // Q: a-frag pairs, tile (bh, s>>7), pos rg*64+d, half = (r&15)>=8
    {
        int qt = s >> 7, r = s & 127;
        int grp = r >> 4, wi = r & 15;
        size_t basei = ((size_t)bh * 16 + qt) * 4096 + (grp * 8 + (wi & 7)) * 64 + d;
        ((unsigned*)Qpk)[basei * 2 + (wi >> 3)] = qo;
    }
    // K: b-frag pairs over d, tile (bh, s>>6)
    {
        int kt = s >> 6, key = s & 63;
        int ks = d >> 3, j = d & 7;
        size_t basei = ((size_t)bh * 32 + kt) * 2048
                     + (ks * 8 + (key >> 3)) * 32 + (key & 7) * 4 + (j & 3);
        ((unsigned*)Kpk)[basei * 2 + (j >> 2)] = ko;
    }
    // V: b-frag pairs over rows, tile (bh, s>>6)
    {
        int kt = s >> 6, rk = s & 63;
        int js = rk >> 3, tg = rk & 7;
        size_t basei = ((size_t)bh * 32 + kt) * 2048
                     + (js * 8 + (d >> 3)) * 32 + (d & 7) * 4 + (tg & 3);
        ((unsigned*)Vpk)[basei * 2 + (tg >> 2)] = vo;
    }
}

// ---------------------------------------------------------------------------
// Flash attention v6: prepacked Q/K/V, cp.async double-buffered K/V,
// Q a-fragments in registers, 1 syncthreads per k-tile.
// ---------------------------------------------------------------------------
#define UQ 68
#define QTILES (Sc / 128)   // 16
#define FP_BYTES (64 * UQ * 8)          // P buffer: 34816
#define FKV_BYTES 16384                 // one K or V tile
#define FSMEM (FP_BYTES + 4 * FKV_BYTES)   // 100352

__global__ __launch_bounds__(256, 2)
void flash_attn_kernel(const uint2* __restrict__ Qpk,
                       const uint2* __restrict__ Kpk,
                       const uint2* __restrict__ Vpk,
                       float* __restrict__ Out) {
    extern __shared__ char fsm[];
    uint2* Pp = (uint2*)fsm;                      // [64][UQ]
    unsigned smem_u;
    asm("{ .reg .u64 t; cvta.to.shared.u64 t, %1; cvt.u32.u64 %0, t; }"
        : "=r"(smem_u) : "l"(fsm));
    const unsigned sK = smem_u + FP_BYTES;
    const unsigned sV = smem_u + FP_BYTES + 2 * FKV_BYTES;

    const int tid = threadIdx.x;
    const int lane = tid & 31;
    const int w = tid >> 5;
    const int g = lane >> 2;
    const int tig = lane & 3;

    const int id = blockIdx.x;
    const int bh = id & 31;
    const int qt = (QTILES - 1) - (id >> 5);
    const int q0 = qt * 128;

    const uint2* Qt = Qpk + ((size_t)bh * 16 + qt) * 4096;
    const uint2* Kb = Kpk + (size_t)bh * 32 * 2048;
    const uint2* Vb = Vpk + (size_t)bh * 32 * 2048;

    // Q a-fragments -> registers (warp-private rows, one-time)
    uint2 qa01[8], qa23[8];
#pragma unroll
    for (int ks = 0; ks < 8; ks++) {
        qa01[ks] = Qt[(w * 8 + g) * 64 + ks * 8 + tig];
        qa23[ks] = Qt[(w * 8 + g) * 64 + ks * 8 + tig + 4];
    }

    auto issue = [&](int kt) {
        const int b = kt & 1;
        const uint2* ksrc = Kb + (size_t)kt * 2048;
        const uint2* vsrc = Vb + (size_t)kt * 2048;
#pragma unroll
        for (int i = 0; i < 4; i++) {
            int e = tid + i * 256;
            cpa16(sK + b * FKV_BYTES + e * 16, ksrc + e * 2);
        }
#pragma unroll
        for (int i = 0; i < 4; i++) {
            int e = tid + i * 256;
            cpa16(sV + b * FKV_BYTES + e * 16, vsrc + e * 2);
        }
        asm volatile("cp.async.commit_group;");
    };

    issue(0);

    float4 s[8], o[8];
#pragma unroll
    for (int t = 0; t < 8; t++) o[t] = make_float4(0.f, 0.f, 0.f, 0.f);
    float mrow0 = -INFINITY, mrow1 = -INFINITY, lrow0 = 0.f, lrow1 = 0.f;

    const int nkt = 2 * qt + 2;
    for (int kt = 0; kt < nkt; kt++) {
        const int b = kt & 1;
        asm volatile("cp.async.wait_group 0;");
        __syncthreads();                      // K[b]/V[b] visible to all
        if (kt + 1 < nkt) issue(kt + 1);      // fills b^1 during compute

        const uint2* Kp = (const uint2*)(fsm + FP_BYTES + (size_t)b * FKV_BYTES);
        const uint2* Vp = (const uint2*)(fsm + FP_BYTES + 2 * FKV_BYTES
                                             + (size_t)b * FKV_BYTES);

        // ---- S = (Q*scale) @ K^T ----
#pragma unroll
        for (int t = 0; t < 8; t++) s[t] = make_float4(0.f, 0.f, 0.f, 0.f);
#pragma unroll
        for (int ks = 0; ks < 8; ks++) {
#pragma unroll
            for (int t = 0; t < 8; t++)
                mma8(s[t], qa01[ks], qa23[ks], Kp[(ks * 8 + t) * 32 + lane]);
        }

        // Causal mask — only on the last two key tiles
        if (kt >= 2 * qt) {
            const int k0 = kt * 64;
            const int r0 = q0 + w * 16 + g;
            const int r1 = r0 + 8;
#pragma unroll
            for (int t = 0; t < 8; t++) {
                int c0 = k0 + t * 8 + 2 * tig;
                if (c0 > r0)     s[t].x = -INFINITY;
                if (c0 + 1 > r0) s[t].y = -INFINITY;
                if (c0 > r1)     s[t].z = -INFINITY;
                if (c0 + 1 > r1) s[t].w = -INFINITY;
            }
        }

        // ---- Online softmax on fragments ----
        float mx0 = -INFINITY, mx1 = -INFINITY;
#pragma unroll
        for (int t = 0; t < 8; t++) {
            mx0 = fmaxf(mx0, fmaxf(s[t].x, s[t].y));
            mx1 = fmaxf(mx1, fmaxf(s[t].z, s[t].w));
        }
        mx0 = fmaxf(mx0, __shfl_xor_sync(0xffffffffu, mx0, 1));
        mx0 = fmaxf(mx0, __shfl_xor_sync(0xffffffffu, mx0, 2));
        mx1 = fmaxf(mx1, __shfl_xor_sync(0xffffffffu, mx1, 1));
        mx1 = fmaxf(mx1, __shfl_xor_sync(0xffffffffu, mx1, 2));
        float mnew0 = fmaxf(mrow0, mx0);
        float mnew1 = fmaxf(mrow1, mx1);
        float cr0 = __expf(mrow0 - mnew0);
        float cr1 = __expf(mrow1 - mnew1);
        float sum0 = 0.f, sum1 = 0.f;
#pragma unroll
        for (int t = 0; t < 8; t++) {
            s[t].x = __expf(s[t].x - mnew0);
            s[t].y = __expf(s[t].y - mnew0);
            s[t].z = __expf(s[t].z - mnew1);
            s[t].w = __expf(s[t].w - mnew1);
            sum0 += s[t].x + s[t].y;
            sum1 += s[t].z + s[t].w;
        }
        sum0 += __shfl_xor_sync(0xffffffffu, sum0, 1);
        sum0 += __shfl_xor_sync(0xffffffffu, sum0, 2);
        sum1 += __shfl_xor_sync(0xffffffffu, sum1, 1);
        sum1 += __shfl_xor_sync(0xffffffffu, sum1, 2);
        lrow0 = lrow0 * cr0 + sum0;
        lrow1 = lrow1 * cr1 + sum1;
        mrow0 = mnew0;
        mrow1 = mnew1;
#pragma unroll
        for (int t = 0; t < 8; t++) {
            o[t].x *= cr0; o[t].y *= cr0;
            o[t].z *= cr1; o[t].w *= cr1;
        }

        // ---- Publish P (warp-private rows; no CTA barrier needed) ----
#pragma unroll
        for (int t = 0; t < 8; t++) {
            uint4 u = make_uint4(f2tf(s[t].x), f2tf(s[t].z),
                                 f2tf(s[t].y), f2tf(s[t].w));
            *(uint4*)&Pp[(w * 8 + g) * UQ + t * 8 + 2 * tig] = u;
        }
        __syncwarp();

        // ---- O += P @ V ----
#pragma unroll
        for (int js = 0; js < 8; js++) {
            uint2 a01 = Pp[(w * 8 + g) * UQ + js * 8 + tig];
            uint2 a23 = Pp[(w * 8 + g) * UQ + js * 8 + tig + 4];
#pragma unroll
            for (int t = 0; t < 8; t++)
                mma8(o[t], a01, a23, Vp[(js * 8 + t) * 32 + lane]);
        }
    }

    // Normalize and write out as [B,S,H*DK]
    const int b = bh >> 4;
    const int h = bh & 15;
    const float inv0 = 1.0f / lrow0;
    const float inv1 = 1.0f / lrow1;
    const size_t row0 = (size_t)(b * Sc + q0 + w * 16 + g) * Dc + h * DKc;
    const size_t row1 = row0 + 8 * Dc;
#pragma unroll
    for (int t = 0; t < 8; t++) {
        *(float2*)&Out[row0 + t * 8 + 2 * tig] =
            make_float2(o[t].x * inv0, o[t].y * inv0);
        *(float2*)&Out[row1 + t * 8 + 2 * tig] =
            make_float2(o[t].z * inv1, o[t].w * inv1);
    }
}

// ---------------------------------------------------------------------------
extern "C" void kernel_launch(void* const* d_in, const int* in_sizes, int n_in,
                              void* d_out, int out_size) {
    const float* x    = (const float*)d_in[0];   // [B,S,D]
    const float* Wqkv = (const float*)d_in[1];   // [D, 3D]
    const float* Wo   = (const float*)d_in[2];   // [D, D]
    float* out = (float*)d_out;

    float *qkv, *attn;
    uint2 *apkx, *bpkq, *apka, *bpkw, *qpk, *kpk, *vpk;
    cudaGetSymbolAddress((void**)&qkv,  g_qkv);
    cudaGetSymbolAddress((void**)&attn, g_attn);
    cudaGetSymbolAddress((void**)&apkx, g_apk_x);
    cudaGetSymbolAddress((void**)&bpkq, g_bpk_qkv);
    cudaGetSymbolAddress((void**)&apka, g_apk_attn);
    cudaGetSymbolAddress((void**)&bpkw, g_bpk_wo);
    cudaGetSymbolAddress((void**)&qpk,  g_qpk);
    cudaGetSymbolAddress((void**)&kpk,  g_kpk);
    cudaGetSymbolAddress((void**)&vpk,  g_vpk);

    // 0. RoPE tables
    rope_table_kernel<<<(Sc * 32) / 256, 256>>>();

    // 1. QKV projection (prepack + cp.async tf32 GEMM)
    prepackA_kernel<<<(BSc * Dc / 2) / 256, 256>>>(x, apkx, Dc);
    prepackB_kernel<<<(Dc * 3 * Dc / 2) / 256, 256>>>(Wqkv, bpkq, 3 * Dc);
    cudaFuncSetAttribute(tgemm_packed,
                         cudaFuncAttributeMaxDynamicSharedMemorySize, SMEM_TOTAL);
    tgemm_packed<<<dim3(3 * Dc / 128, BSc / 128), 256, SMEM_TOTAL>>>(
        apkx, bpkq, qkv, BSc, 3 * Dc);

    // 2. RoPE + fragment-pack Q/K/V
    rope_pack_kernel<<<(Bc * Sc * Hc * DKc) / 256, 256>>>(qkv, qpk, kpk, vpk);

    // 3. Causal flash attention (prepacked, cp.async double-buffered)
    cudaFuncSetAttribute(flash_attn_kernel,
                         cudaFuncAttributeMaxDynamicSharedMemorySize, FSMEM);
    flash_attn_kernel<<<32 * QTILES, 256, FSMEM>>>(qpk, kpk, vpk, attn);

    // 4. Output projection (prepack + cp.async tf32 GEMM)
    prepackA_kernel<<<(BSc * Dc / 2) / 256, 256>>>(attn, apka, Dc);
    prepackB_kernel<<<(Dc * Dc / 2) / 256, 256>>>(Wo, bpkw, Dc);
    tgemm_packed<<<dim3(Dc / 128, BSc / 128), 256, SMEM_TOTAL>>>(
        apka, bpkw, out, BSc, Dc);
}

// round 12
// speedup vs baseline: 2.1173x; 1.0011x over previous
#include <cuda_runtime.h>
#include <math.h>

#define Bc 2
#define Sc 2048
#define Dc 1024
#define Hc 16
#define DKc 64
#define BSc (Bc*Sc)   // 4096

// Scratch (no allocations allowed)
__device__ float g_qkv[(size_t)BSc * 3 * Dc];      // [B,S,3,H,DK]
__device__ float g_attn[(size_t)BSc * Dc];         // [B,S,D]
__device__ float g_ctab[Sc * 32];                  // RoPE cos table
__device__ float g_stab[Sc * 32];                  // RoPE sin table

// Packed tf32 tile buffers for the GEMMs (tile-major, fragment order)
__device__ uint2 g_apk_x[(size_t)BSc * Dc / 2];
__device__ uint2 g_bpk_qkv[(size_t)Dc * 3 * Dc / 2];
__device__ uint2 g_apk_attn[(size_t)BSc * Dc / 2];
__device__ uint2 g_bpk_wo[(size_t)Dc * Dc / 2];

// Packed tf32 Q/K/V for flash (written by rope_pack)
__device__ uint2 g_qpk[(size_t)32 * 16 * 4096];    // [bh][qt128] a-frag pairs
__device__ uint2 g_kpk[(size_t)32 * 32 * 2048];    // [bh][kt64]  b-frag pairs
__device__ uint2 g_vpk[(size_t)32 * 32 * 2048];    // [bh][kt64]  b-frag pairs

__device__ __forceinline__ unsigned f2tf(float x) {
    unsigned r;
    asm("cvt.rna.tf32.f32 %0, %1;" : "=r"(r) : "f"(x));
    return r;
}

__device__ __forceinline__ void mma8(float4& d, uint2 a01, uint2 a23, uint2 b) {
    asm volatile(
        "mma.sync.aligned.m16n8k8.row.col.f32.tf32.tf32.f32 "
        "{%0,%1,%2,%3}, {%4,%5,%6,%7}, {%8,%9}, {%0,%1,%2,%3};\n"
        : "+f"(d.x), "+f"(d.y), "+f"(d.z), "+f"(d.w)
        : "r"(a01.x), "r"(a01.y), "r"(a23.x), "r"(a23.y), "r"(b.x), "r"(b.y));
}

__device__ __forceinline__ void cpa16(unsigned dst, const void* src) {
    asm volatile("cp.async.cg.shared.global [%0], [%1], 16;"
                 :: "r"(dst), "l"(src));
}

// ---------------------------------------------------------------------------
// Pre-pack A[M,K=1024] -> tile-major a-fragment pairs (unchanged from R10)
// ---------------------------------------------------------------------------
__global__ void prepackA_kernel(const float* __restrict__ A,
                                uint2* __restrict__ out, int K) {
    int idx = blockIdx.x * blockDim.x + threadIdx.x;
    int k = idx & 31;
    int rg = (idx >> 5) & 63;
    int ck = idx >> 11;
    int kt = ck & 31;
    int mt = ck >> 5;
    int r = mt * 128 + ((rg >> 3) << 4) + (rg & 7);
    int col = kt * 32 + k;
    out[idx] = make_uint2(f2tf(A[(size_t)r * K + col]),
                          f2tf(A[(size_t)(r + 8) * K + col]));
}

// ---------------------------------------------------------------------------
// Pre-pack B[K=1024,N] -> tile-major b-fragment pairs (unchanged from R10)
// ---------------------------------------------------------------------------
__global__ void prepackB_kernel(const float* __restrict__ B,
                                uint2* __restrict__ out, int N) {
    int idx = blockIdx.x * blockDim.x + threadIdx.x;
    int pos = idx & 2047;
    int ck = idx >> 11;
    int kt = ck & 31;
    int nt = ck >> 5;
    int tg = pos & 3;
    int col = (((pos >> 5) & 15) << 3) + ((pos >> 2) & 7);
    int ks = pos >> 9;
    int row = kt * 32 + ks * 8 + tg;
    int c = nt * 128 + col;
    out[idx] = make_uint2(f2tf(B[(size_t)row * N + c]),
                          f2tf(B[(size_t)(row + 4) * N + c]));
}

// ---------------------------------------------------------------------------
// tf32 GEMM on prepacked tiles, cp.async double-buffered (unchanged from R10)
// ---------------------------------------------------------------------------
#define AS 36
#define BUFA_BYTES (64 * AS * 8)
#define BUFB_BYTES (64 * 32 * 8)
#define SMEM_TOTAL (2 * (BUFA_BYTES + BUFB_BYTES))   // 69632

__global__ __launch_bounds__(256, 2)
void tgemm_packed(const uint2* __restrict__ Apk,
                  const uint2* __restrict__ Bpk,
                  float* __restrict__ C, int M, int N) {
    extern __shared__ char smraw[];
    unsigned smem_u;
    asm("{ .reg .u64 t; cvta.to.shared.u64 t, %1; cvt.u32.u64 %0, t; }"
        : "=r"(smem_u) : "l"(smraw));
    const unsigned sA0 = smem_u;
    const unsigned sB0 = smem_u + 2 * BUFA_BYTES;

    const int tid = threadIdx.x;
    const int lane = tid & 31;
    const int w = tid >> 5;
    const int g = lane >> 2;
    const int tig = lane & 3;
    const int wm = w >> 2;
    const int wn = w & 3;
    const int mt_blk = blockIdx.y;
    const int nt_blk = blockIdx.x;

    const uint2* Abase = Apk + (size_t)mt_blk * 32 * 2048;
    const uint2* Bbase = Bpk + (size_t)nt_blk * 32 * 2048;

    auto issue = [&](int kt, int b) {
        const uint2* at = Abase + (size_t)kt * 2048;
        const uint2* bt = Bbase + (size_t)kt * 2048;
        unsigned dA = sA0 + b * BUFA_BYTES;
        unsigned dB = sB0 + b * BUFB_BYTES;
#pragma unroll
        for (int i = 0; i < 4; i++) {
            int e = tid + i * 256;
            int rg = e >> 4, c = e & 15;
            cpa16(dA + rg * (AS * 8) + c * 16, at + e * 2);
        }
#pragma unroll
        for (int i = 0; i < 4; i++) {
            int e = tid + i * 256;
            cpa16(dB + e * 16, bt + e * 2);
        }
        asm volatile("cp.async.commit_group;");
    };

    issue(0, 0);

    float4 acc[4][4];
#pragma unroll
    for (int i = 0; i < 4; i++)
#pragma unroll
        for (int j = 0; j < 4; j++) acc[i][j] = make_float4(0.f, 0.f, 0.f, 0.f);

    for (int kt = 0; kt < 32; kt++) {
        const int b = kt & 1;
        if (kt + 1 < 32) {
            issue(kt + 1, b ^ 1);
            asm volatile("cp.async.wait_group 1;");
        } else {
            asm volatile("cp.async.wait_group 0;");
        }
        __syncthreads();

        const uint2* Ap = (const uint2*)(smraw + (size_t)b * BUFA_BYTES);
        const uint2* Bp = (const uint2*)(smraw + 2 * BUFA_BYTES
                                               + (size_t)b * BUFB_BYTES);
#pragma unroll
        for (int ks = 0; ks < 4; ks++) {
            uint2 bfr[4];
#pragma unroll
            for (int nt = 0; nt < 4; nt++)
                bfr[nt] = Bp[(ks * 16 + wn * 4 + nt) * 32 + lane];
#pragma unroll
            for (int mt = 0; mt < 4; mt++) {
                uint2 a01 = Ap[(wm * 32 + mt * 8 + g) * AS + ks * 8 + tig];
                uint2 a23 = Ap[(wm * 32 + mt * 8 + g) * AS + ks * 8 + tig + 4];
#pragma unroll
                for (int nt = 0; nt < 4; nt++)
                    mma8(acc[mt][nt], a01, a23, bfr[nt]);
            }
        }
        __syncthreads();
    }

    const int m0 = mt_blk << 7;
    const int n0 = nt_blk << 7;
#pragma unroll
    for (int mt = 0; mt < 4; mt++) {
        int row = m0 + wm * 64 + mt * 16 + g;
#pragma unroll
        for (int nt = 0; nt < 4; nt++) {
            int col = n0 + wn * 32 + nt * 8 + 2 * tig;
            *(float2*)&C[(size_t)row * N + col] =
                make_float2(acc[mt][nt].x, acc[mt][nt].y);
            *(float2*)&C[(size_t)(row + 8) * N + col] =
                make_float2(acc[mt][nt].z, acc[mt][nt].w);
        }
    }
}

// ---------------------------------------------------------------------------
// RoPE table precompute (unchanged)
// ---------------------------------------------------------------------------
__global__ void rope_table_kernel() {
    int idx = blockIdx.x * blockDim.x + threadIdx.x;
    int d2 = idx & 31;
    int s = idx >> 5;
    float invf = 1.0f / powf(10000.0f, (float)d2 * (1.0f / 32.0f));
    float ang = (float)s * invf;
    float sn, c;
    sincosf(ang, &sn, &c);
    g_ctab[idx] = c;
    g_stab[idx] = sn;
}

// ---------------------------------------------------------------------------
// RoPE + pack: applies rotary, then writes Q/K/V directly in the tf32
// fragment-packed tile layouts flash consumes. Same arithmetic as before
// (fp32 rope -> [scale] -> cvt.rna.tf32), just relocated.
// ---------------------------------------------------------------------------
__global__ void rope_pack_kernel(const float* __restrict__ qkv,
                                 uint2* __restrict__ Qpk,
                                 uint2* __restrict__ Kpk,
                                 uint2* __restrict__ Vpk) {
    int idx = blockIdx.x * blockDim.x + threadIdx.x;  // [b][s][h][d]
    int d = idx & 63;
    int h = (idx >> 6) & (Hc - 1);
    int s = (idx >> 10) & (Sc - 1);
    int b = idx >> 21;

    const float* base = qkv + (size_t)(b * Sc + s) * 3 * Dc + h * DKc;
    float qv = base[d];
    float kv = base[Dc + d];
    float vv = base[2 * Dc + d];

    int d2 = d & 31;
    float c = g_ctab[s * 32 + d2];
    float sn = g_stab[s * 32 + d2];

    int dp = d ^ 32;
    float qp = base[dp];
    float kp = base[Dc + dp];
    float sgn = (d < 32) ? -1.0f : 1.0f;

    unsigned qo = f2tf((qv * c + sgn * qp * sn) * 0.125f);  // fold 1/sqrt(dk)
    unsigned ko = f2tf(kv * c + sgn * kp * sn);
    unsigned vo = f2tf(vv);

    const int bh = b * Hc + h;

    // Q: a-frag pairs, tile (bh, s>>7), pos rg*64+d, half = (r&15)>=8
    {
        int qt = s >> 7, r = s & 127;
        int grp = r >> 4, wi = r & 15;
        size_t basei = ((size_t)bh * 16 + qt) * 4096 + (grp * 8 + (wi & 7)) * 64 + d;
        ((unsigned*)Qpk)[basei * 2 + (wi >> 3)] = qo;
    }
    // K: b-frag pairs over d, tile (bh, s>>6)
    {
        int kt = s >> 6, key = s & 63;
        int ks = d >> 3, j = d & 7;
        size_t basei = ((size_t)bh * 32 + kt) * 2048
                     + (ks * 8 + (key >> 3)) * 32 + (key & 7) * 4 + (j & 3);
        ((unsigned*)Kpk)[basei * 2 + (j >> 2)] = ko;
    }
    // V: b-frag pairs over rows, tile (bh, s>>6)
    {
        int kt = s >> 6, rk = s & 63;
        int js = rk >> 3, tg = rk & 7;
        size_t basei = ((size_t)bh * 32 + kt) * 2048
                     + (js * 8 + (d >> 3)) * 32 + (d & 7) * 4 + (tg & 3);
        ((unsigned*)Vpk)[basei * 2 + (tg >> 2)] = vo;
    }
}

// ---------------------------------------------------------------------------
// Flash attention v6: prepacked Q/K/V, cp.async double-buffered K/V,
// Q a-fragments in registers, 1 syncthreads per k-tile.
// ---------------------------------------------------------------------------
#define UQ 68
#define QTILES (Sc / 128)   // 16
#define FP_BYTES (64 * UQ * 8)          // P buffer: 34816
#define FKV_BYTES 16384                 // one K or V tile
#define FSMEM (FP_BYTES + 4 * FKV_BYTES)   // 100352

__global__ __launch_bounds__(256, 2)
void flash_attn_kernel(const uint2* __restrict__ Qpk,
                       const uint2* __restrict__ Kpk,
                       const uint2* __restrict__ Vpk,
                       float* __restrict__ Out) {
    extern __shared__ char fsm[];
    uint2* Pp = (uint2*)fsm;                      // [64][UQ]
    unsigned smem_u;
    asm("{ .reg .u64 t; cvta.to.shared.u64 t, %1; cvt.u32.u64 %0, t; }"
        : "=r"(smem_u) : "l"(fsm));
    const unsigned sK = smem_u + FP_BYTES;
    const unsigned sV = smem_u + FP_BYTES + 2 * FKV_BYTES;

    const int tid = threadIdx.x;
    const int lane = tid & 31;
    const int w = tid >> 5;
    const int g = lane >> 2;
    const int tig = lane & 3;

    const int id = blockIdx.x;
    const int bh = id & 31;
    const int qt = (QTILES - 1) - (id >> 5);
    const int q0 = qt * 128;

    const uint2* Qt = Qpk + ((size_t)bh * 16 + qt) * 4096;
    const uint2* Kb = Kpk + (size_t)bh * 32 * 2048;
    const uint2* Vb = Vpk + (size_t)bh * 32 * 2048;

    // Q a-fragments -> registers (warp-private rows, one-time)
    uint2 qa01[8], qa23[8];
#pragma unroll
    for (int ks = 0; ks < 8; ks++) {
        qa01[ks] = Qt[(w * 8 + g) * 64 + ks * 8 + tig];
        qa23[ks] = Qt[(w * 8 + g) * 64 + ks * 8 + tig + 4];
    }

    auto issue = [&](int kt) {
        const int b = kt & 1;
        const uint2* ksrc = Kb + (size_t)kt * 2048;
        const uint2* vsrc = Vb + (size_t)kt * 2048;
#pragma unroll
        for (int i = 0; i < 4; i++) {
            int e = tid + i * 256;
            cpa16(sK + b * FKV_BYTES + e * 16, ksrc + e * 2);
        }
#pragma unroll
        for (int i = 0; i < 4; i++) {
            int e = tid + i * 256;
            cpa16(sV + b * FKV_BYTES + e * 16, vsrc + e * 2);
        }
        asm volatile("cp.async.commit_group;");
    };

    issue(0);

    float4 s[8], o[8];
#pragma unroll
    for (int t = 0; t < 8; t++) o[t] = make_float4(0.f, 0.f, 0.f, 0.f);
    float mrow0 = -INFINITY, mrow1 = -INFINITY, lrow0 = 0.f, lrow1 = 0.f;

    const int nkt = 2 * qt + 2;
    for (int kt = 0; kt < nkt; kt++) {
        const int b = kt & 1;
        asm volatile("cp.async.wait_group 0;");
        __syncthreads();                      // K[b]/V[b] visible to all
        if (kt + 1 < nkt) issue(kt + 1);      // fills b^1 during compute

        const uint2* Kp = (const uint2*)(fsm + FP_BYTES + (size_t)b * FKV_BYTES);
        const uint2* Vp = (const uint2*)(fsm + FP_BYTES + 2 * FKV_BYTES
                                             + (size_t)b * FKV_BYTES);

        // ---- S = (Q*scale) @ K^T ----
#pragma unroll
        for (int t = 0; t < 8; t++) s[t] = make_float4(0.f, 0.f, 0.f, 0.f);
#pragma unroll
        for (int ks = 0; ks < 8; ks++) {
#pragma unroll
            for (int t = 0; t < 8; t++)
                mma8(s[t], qa01[ks], qa23[ks], Kp[(ks * 8 + t) * 32 + lane]);
        }

        // Causal mask — only on the last two key tiles
        if (kt >= 2 * qt) {
            const int k0 = kt * 64;
            const int r0 = q0 + w * 16 + g;
            const int r1 = r0 + 8;
#pragma unroll
            for (int t = 0; t < 8; t++) {
                int c0 = k0 + t * 8 + 2 * tig;
                if (c0 > r0)     s[t].x = -INFINITY;
                if (c0 + 1 > r0) s[t].y = -INFINITY;
                if (c0 > r1)     s[t].z = -INFINITY;
                if (c0 + 1 > r1) s[t].w = -INFINITY;
            }
        }

        // ---- Online softmax on fragments ----
        float mx0 = -INFINITY, mx1 = -INFINITY;
#pragma unroll
        for (int t = 0; t < 8; t++) {
            mx0 = fmaxf(mx0, fmaxf(s[t].x, s[t].y));
            mx1 = fmaxf(mx1, fmaxf(s[t].z, s[t].w));
        }
        mx0 = fmaxf(mx0, __shfl_xor_sync(0xffffffffu, mx0, 1));
        mx0 = fmaxf(mx0, __shfl_xor_sync(0xffffffffu, mx0, 2));
        mx1 = fmaxf(mx1, __shfl_xor_sync(0xffffffffu, mx1, 1));
        mx1 = fmaxf(mx1, __shfl_xor_sync(0xffffffffu, mx1, 2));
        float mnew0 = fmaxf(mrow0, mx0);
        float mnew1 = fmaxf(mrow1, mx1);
        float cr0 = __expf(mrow0 - mnew0);
        float cr1 = __expf(mrow1 - mnew1);
        float sum0 = 0.f, sum1 = 0.f;
#pragma unroll
        for (int t = 0; t < 8; t++) {
            s[t].x = __expf(s[t].x - mnew0);
            s[t].y = __expf(s[t].y - mnew0);
            s[t].z = __expf(s[t].z - mnew1);
            s[t].w = __expf(s[t].w - mnew1);
            sum0 += s[t].x + s[t].y;
            sum1 += s[t].z + s[t].w;
        }
        sum0 += __shfl_xor_sync(0xffffffffu, sum0, 1);
        sum0 += __shfl_xor_sync(0xffffffffu, sum0, 2);
        sum1 += __shfl_xor_sync(0xffffffffu, sum1, 1);
        sum1 += __shfl_xor_sync(0xffffffffu, sum1, 2);
        lrow0 = lrow0 * cr0 + sum0;
        lrow1 = lrow1 * cr1 + sum1;
        mrow0 = mnew0;
        mrow1 = mnew1;
#pragma unroll
        for (int t = 0; t < 8; t++) {
            o[t].x *= cr0; o[t].y *= cr0;
            o[t].z *= cr1; o[t].w *= cr1;
        }

        // ---- Publish P (warp-private rows; no CTA barrier needed) ----
#pragma unroll
        for (int t = 0; t < 8; t++) {
            uint4 u = make_uint4(f2tf(s[t].x), f2tf(s[t].z),
                                 f2tf(s[t].y), f2tf(s[t].w));
            *(uint4*)&Pp[(w * 8 + g) * UQ + t * 8 + 2 * tig] = u;
        }
        __syncwarp();

        // ---- O += P @ V ----
#pragma unroll
        for (int js = 0; js < 8; js++) {
            uint2 a01 = Pp[(w * 8 + g) * UQ + js * 8 + tig];
            uint2 a23 = Pp[(w * 8 + g) * UQ + js * 8 + tig + 4];
#pragma unroll
            for (int t = 0; t < 8; t++)
                mma8(o[t], a01, a23, Vp[(js * 8 + t) * 32 + lane]);
        }
    }

    // Normalize and write out as [B,S,H*DK]
    const int b = bh >> 4;
    const int h = bh & 15;
    const float inv0 = 1.0f / lrow0;
    const float inv1 = 1.0f / lrow1;
    const size_t row0 = (size_t)(b * Sc + q0 + w * 16 + g) * Dc + h * DKc;
    const size_t row1 = row0 + 8 * Dc;
#pragma unroll
    for (int t = 0; t < 8; t++) {
        *(float2*)&Out[row0 + t * 8 + 2 * tig] =
            make_float2(o[t].x * inv0, o[t].y * inv0);
        *(float2*)&Out[row1 + t * 8 + 2 * tig] =
            make_float2(o[t].z * inv1, o[t].w * inv1);
    }
}

// ---------------------------------------------------------------------------
extern "C" void kernel_launch(void* const* d_in, const int* in_sizes, int n_in,
                              void* d_out, int out_size) {
    const float* x    = (const float*)d_in[0];   // [B,S,D]
    const float* Wqkv = (const float*)d_in[1];   // [D, 3D]
    const float* Wo   = (const float*)d_in[2];   // [D, D]
    float* out = (float*)d_out;

    float *qkv, *attn;
    uint2 *apkx, *bpkq, *apka, *bpkw, *qpk, *kpk, *vpk;
    cudaGetSymbolAddress((void**)&qkv,  g_qkv);
    cudaGetSymbolAddress((void**)&attn, g_attn);
    cudaGetSymbolAddress((void**)&apkx, g_apk_x);
    cudaGetSymbolAddress((void**)&bpkq, g_bpk_qkv);
    cudaGetSymbolAddress((void**)&apka, g_apk_attn);
    cudaGetSymbolAddress((void**)&bpkw, g_bpk_wo);
    cudaGetSymbolAddress((void**)&qpk,  g_qpk);
    cudaGetSymbolAddress((void**)&kpk,  g_kpk);
    cudaGetSymbolAddress((void**)&vpk,  g_vpk);

    // 0. RoPE tables
    rope_table_kernel<<<(Sc * 32) / 256, 256>>>();

    // 1. QKV projection (prepack + cp.async tf32 GEMM)
    prepackA_kernel<<<(BSc * Dc / 2) / 256, 256>>>(x, apkx, Dc);
    prepackB_kernel<<<(Dc * 3 * Dc / 2) / 256, 256>>>(Wqkv, bpkq, 3 * Dc);
    cudaFuncSetAttribute(tgemm_packed,
                         cudaFuncAttributeMaxDynamicSharedMemorySize, SMEM_TOTAL);
    tgemm_packed<<<dim3(3 * Dc / 128, BSc / 128), 256, SMEM_TOTAL>>>(
        apkx, bpkq, qkv, BSc, 3 * Dc);

    // 2. RoPE + fragment-pack Q/K/V
    rope_pack_kernel<<<(Bc * Sc * Hc * DKc) / 256, 256>>>(qkv, qpk, kpk, vpk);

    // 3. Causal flash attention (prepacked, cp.async double-buffered)
    cudaFuncSetAttribute(flash_attn_kernel,
                         cudaFuncAttributeMaxDynamicSharedMemorySize, FSMEM);
    flash_attn_kernel<<<32 * QTILES, 256, FSMEM>>>(qpk, kpk, vpk, attn);

    // 4. Output projection (prepack + cp.async tf32 GEMM)
    prepackA_kernel<<<(BSc * Dc / 2) / 256, 256>>>(attn, apka, Dc);
    prepackB_kernel<<<(Dc * Dc / 2) / 256, 256>>>(Wo, bpkw, Dc);
    tgemm_packed<<<dim3(Dc / 128, BSc / 128), 256, SMEM_TOTAL>>>(
        apka, bpkw, out, BSc, Dc);
}